// round 9
// baseline (speedup 1.0000x reference)
#include <cuda_runtime.h>
#include <stdint.h>

// Problem constants
#define BATCH 16
#define LQ 2048
#define LK 2048
#define DH 64

// Block = 64 q-rows x full LK. 256 threads (8 warps).
// Warp w: row-group wg = w&3 (rows wg*16..+16), k-half = w>>2 (tiles half*16..+16).
#define BQ 64
#define BK 64
#define NT 256
#define NTILES (LK / BK)     // 32
#define HTILES (NTILES / 2)  // 16 per warp-group
#define KSTR 72              // k smem row stride in floats (frag layout, conflict-free LDS.64)

#define OUT_ELEMS  ((size_t)BATCH * LQ * DH)   // 2,097,152
#define ATTN_ELEMS ((size_t)BATCH * LQ * LK)   // 67,108,864

#define REPAIR_EPS 0.2f

__device__ __forceinline__ float ex2a(float x) {
    float r; asm("ex2.approx.ftz.f32 %0, %1;" : "=f"(r) : "f"(x)); return r;
}
__device__ __forceinline__ unsigned cvt_tf32(float x) {
    unsigned r; asm("cvt.rna.tf32.f32 %0, %1;" : "=r"(r) : "f"(x)); return r;
}
__device__ __forceinline__ void mma_tf32(float c[4],
                                         unsigned a0, unsigned a1, unsigned a2, unsigned a3,
                                         unsigned b0, unsigned b1) {
    asm volatile("mma.sync.aligned.m16n8k8.row.col.f32.tf32.tf32.f32 "
                 "{%0,%1,%2,%3}, {%4,%5,%6,%7}, {%8,%9}, {%0,%1,%2,%3};"
                 : "+f"(c[0]), "+f"(c[1]), "+f"(c[2]), "+f"(c[3])
                 : "r"(a0), "r"(a1), "r"(a2), "r"(a3), "r"(b0), "r"(b1));
}

__global__ __launch_bounds__(NT)
void wta_attn9_kernel(const float* __restrict__ q,
                      const float* __restrict__ k,
                      const float* __restrict__ v,
                      float* __restrict__ out,
                      int write_out, int write_attn, long long attn_off)
{
    // k tiles in mma-fragment order:
    //   element (krow, d) at word  (d>>3)*8 + (d&3)*2 + ((d>>2)&1)  ^  ((krow&3)<<1)
    // so thread (l4,lm)'s (b0,b1) pair for slice s is one aligned 8-byte LDS.
    __shared__ float ks[2][BK][KSTR];          // 36.9 KB
    __shared__ float tilemax[BQ][NTILES];      //  8  KB
    __shared__ float rs[2][BQ];
    __shared__ float rowsum[BQ];
    __shared__ float pval[BQ];
    __shared__ int   widx[BQ];

    const int b    = blockIdx.y;
    const int q0   = blockIdx.x * BQ;
    const int tid  = threadIdx.x;
    const int w    = tid >> 5;
    const int lane = tid & 31;
    const int wg   = w & 3;        // row group
    const int half = w >> 2;       // k half
    const int l4   = lane >> 2;
    const int lm   = lane & 3;

    const float* qb = q + ((size_t)b * LQ + q0) * DH;
    const float* kb = k + (size_t)b * LK * DH;

    const int r0 = wg * 16 + l4;
    const int r1 = r0 + 8;

    // ---- A fragments (q): tf32 once, resident in regs ----
    unsigned Af[8][4];
    #pragma unroll
    for (int s = 0; s < 8; s++) {
        Af[s][0] = cvt_tf32(qb[(size_t)r0 * DH + s * 8 + lm]);
        Af[s][1] = cvt_tf32(qb[(size_t)r1 * DH + s * 8 + lm]);
        Af[s][2] = cvt_tf32(qb[(size_t)r0 * DH + s * 8 + lm + 4]);
        Af[s][3] = cvt_tf32(qb[(size_t)r1 * DH + s * 8 + lm + 4]);
    }

    const float C = 0.18033688011112042f;   // 0.125 * log2(e)
    float sum0 = 0.0f, sum1 = 0.0f;

    float4* az = 0;
    if (write_attn)
        az = (float4*)(out + attn_off + ((size_t)b * LQ + q0) * LK);

    // ================= mainloop: 16 iterations, 2 tiles resident =================
    for (int it = 0; it < HTILES; it++) {
        __syncthreads();

        // load tile it -> buf0, tile it+16 -> buf1; cvt tf32; fragment-order STS
        #pragma unroll
        for (int i = 0; i < 8; i++) {
            int fi   = tid + i * NT;       // 0..2047
            int buf  = fi >> 10;
            int wi   = fi & 1023;
            int krow = wi >> 4;
            int c4   = wi & 15;
            const float4* src = (const float4*)(kb + (size_t)(it + buf * HTILES) * BK * DH);
            float4 wv = src[wi];
            float* dst = &ks[buf][krow][0];
            const int swz  = (krow & 3) << 1;
            const int base = (c4 >> 1) * 8 + (c4 & 1);   // s*8 + half
            dst[(base + 0) ^ swz] = __uint_as_float(cvt_tf32(wv.x));
            dst[(base + 2) ^ swz] = __uint_as_float(cvt_tf32(wv.y));
            dst[(base + 4) ^ swz] = __uint_as_float(cvt_tf32(wv.z));
            dst[(base + 6) ^ swz] = __uint_as_float(cvt_tf32(wv.w));
        }

        // interleaved zero-fill: chunks for tiles it and it+16
        if (write_attn) {
            #pragma unroll
            for (int j = 0; j < 8; j++) {
                int fi  = tid + j * NT;
                int buf = fi >> 10;
                int wi  = fi & 1023;
                az[(size_t)(it + buf * HTILES) * (BQ * BK / 4) + wi] =
                    make_float4(0.f, 0.f, 0.f, 0.f);
            }
        }
        __syncthreads();

        const int t = it + half * HTILES;

        float acc[8][4];
        #pragma unroll
        for (int n = 0; n < 8; n++)
            #pragma unroll
            for (int c = 0; c < 4; c++) acc[n][c] = 0.0f;

        #pragma unroll
        for (int n = 0; n < 8; n++) {
            // this thread's fragment words for row n*8+l4: one LDS.64 per slice s
            const float* rp = &ks[half][n * 8 + l4][(lm * 2) ^ ((l4 & 3) << 1)];
            #pragma unroll
            for (int s = 0; s < 8; s++) {
                unsigned long long bv = *(const unsigned long long*)(rp + s * 8);
                mma_tf32(acc[n], Af[s][0], Af[s][1], Af[s][2], Af[s][3],
                         (unsigned)(bv & 0xffffffffu), (unsigned)(bv >> 32));
            }
        }

        float tm0 = -1e30f, tm1 = -1e30f;
        #pragma unroll
        for (int n = 0; n < 8; n++) {
            tm0 = fmaxf(tm0, fmaxf(acc[n][0], acc[n][1]));
            tm1 = fmaxf(tm1, fmaxf(acc[n][2], acc[n][3]));
            sum0 += ex2a(acc[n][0] * C) + ex2a(acc[n][1] * C);
            sum1 += ex2a(acc[n][2] * C) + ex2a(acc[n][3] * C);
        }
        #pragma unroll
        for (int off = 1; off <= 2; off <<= 1) {
            tm0 = fmaxf(tm0, __shfl_xor_sync(0xffffffffu, tm0, off));
            tm1 = fmaxf(tm1, __shfl_xor_sync(0xffffffffu, tm1, off));
        }
        if (lm == 0) { tilemax[r0][t] = tm0; tilemax[r1][t] = tm1; }
    }

    // partial row sums per half
    #pragma unroll
    for (int off = 1; off <= 2; off <<= 1) {
        sum0 += __shfl_xor_sync(0xffffffffu, sum0, off);
        sum1 += __shfl_xor_sync(0xffffffffu, sum1, off);
    }
    if (lm == 0) { rs[half][r0] = sum0; rs[half][r1] = sum1; }
    __syncthreads();

    if (tid < BQ) rowsum[tid] = rs[0][tid] + rs[1][tid];
    __syncthreads();

    // ================= repair: one warp per row, warp-uniform branches =================
    #pragma unroll 1
    for (int rr8 = 0; rr8 < BQ / 8; rr8++) {
        const int r = w * 8 + rr8;

        const float tmv = tilemax[r][lane];      // 32 lanes = 32 tiles
        float best = tmv;
        #pragma unroll
        for (int off = 16; off > 0; off >>= 1)
            best = fmaxf(best, __shfl_xor_sync(0xffffffffu, best, off));
        const float thr = best - REPAIR_EPS;

        const float4 qv = *(const float4*)(qb + (size_t)r * DH + (lane & 15) * 4);

        float bm = -1e30f;
        int   bi = 0;
        #pragma unroll 1
        for (int t = 0; t < NTILES; t++) {
            if (__shfl_sync(0xffffffffu, tmv, t) < thr) continue;   // warp-uniform
            const float* kt = kb + (size_t)t * BK * DH;
            #pragma unroll 4
            for (int rr = 0; rr < 32; rr++) {
                const int col = rr * 2 + (lane >> 4);
                const float4 kv = *(const float4*)(kt + (size_t)col * DH + (lane & 15) * 4);
                float p = fmaf(qv.x, kv.x, fmaf(qv.y, kv.y,
                          fmaf(qv.z, kv.z, qv.w * kv.w)));
                p += __shfl_xor_sync(0xffffffffu, p, 8, 16);
                p += __shfl_xor_sync(0xffffffffu, p, 4, 16);
                p += __shfl_xor_sync(0xffffffffu, p, 2, 16);
                p += __shfl_xor_sync(0xffffffffu, p, 1, 16);
                if (p > bm) { bm = p; bi = t * BK + col; }  // strict > : lowest t/col kept
            }
        }
        #pragma unroll
        for (int off = 16; off > 0; off >>= 1) {
            float om = __shfl_xor_sync(0xffffffffu, bm, off);
            int   oi = __shfl_xor_sync(0xffffffffu, bi, off);
            if (om > bm || (om == bm && oi < bi)) { bm = om; bi = oi; }
        }
        if (lane == 0) {
            float p = ex2a(bm * C) / rowsum[r];
            pval[r] = p;
            widx[r] = bi;
            if (write_attn)
                out[attn_off + ((size_t)b * LQ + q0 + r) * LK + bi] = p;
        }
    }
    __syncthreads();

    // ================= dense output =================
    if (write_out) {
        #pragma unroll
        for (int i = tid; i < BQ * (DH / 4); i += NT) {
            const int r = i >> 4;
            const int c = i & 15;
            const float p = pval[r];
            const float4 vv = *(const float4*)(v + ((size_t)b * LK + widx[r]) * DH + c * 4);
            float4 o;
            o.x = p * vv.x; o.y = p * vv.y; o.z = p * vv.z; o.w = p * vv.w;
            *(float4*)(out + ((size_t)b * LQ + q0 + r) * DH + c * 4) = o;
        }
    }
}

extern "C" void kernel_launch(void* const* d_in, const int* in_sizes, int n_in,
                              void* d_out, int out_size)
{
    const float* q = (const float*)d_in[0];
    const float* k = (const float*)d_in[1];
    const float* v = (const float*)d_in[2];
    float* out = (float*)d_out;

    int wout = 0, wattn = 0;
    long long aoff = 0;
    size_t osz = (size_t)out_size;
    if (osz == OUT_ELEMS + ATTN_ELEMS) { wout = 1; wattn = 1; aoff = (long long)OUT_ELEMS; }
    else if (osz == ATTN_ELEMS)        { wattn = 1; aoff = 0; }
    else                               { wout = 1; }

    dim3 grid(LQ / BQ, BATCH);
    wta_attn9_kernel<<<grid, NT>>>(q, k, v, out, wout, wattn, aoff);
}

// round 10
// speedup vs baseline: 1.0388x; 1.0388x over previous
#include <cuda_runtime.h>
#include <stdint.h>

// Problem constants
#define BATCH 16
#define LQ 2048
#define LK 2048
#define DH 64

// Block = 64 q-rows x full LK. 256 threads (8 warps).
// Warp w: row-group wg = w&3 (rows wg*16..+16), k-half = w>>2 (tiles half*16..+16).
#define BQ 64
#define BK 64
#define NT 256
#define NTILES (LK / BK)     // 32
#define HTILES (NTILES / 2)  // 16 per warp-group
#define KPAD 68

#define OUT_ELEMS  ((size_t)BATCH * LQ * DH)   // 2,097,152
#define ATTN_ELEMS ((size_t)BATCH * LQ * LK)   // 67,108,864

#define REPAIR_EPS 0.2f

__device__ __forceinline__ float ex2a(float x) {
    float r; asm("ex2.approx.ftz.f32 %0, %1;" : "=f"(r) : "f"(x)); return r;
}
__device__ __forceinline__ unsigned cvt_tf32(float x) {
    unsigned r; asm("cvt.rna.tf32.f32 %0, %1;" : "=r"(r) : "f"(x)); return r;
}
__device__ __forceinline__ void mma_tf32(float c[4],
                                         unsigned a0, unsigned a1, unsigned a2, unsigned a3,
                                         unsigned b0, unsigned b1) {
    asm volatile("mma.sync.aligned.m16n8k8.row.col.f32.tf32.tf32.f32 "
                 "{%0,%1,%2,%3}, {%4,%5,%6,%7}, {%8,%9}, {%0,%1,%2,%3};"
                 : "+f"(c[0]), "+f"(c[1]), "+f"(c[2]), "+f"(c[3])
                 : "r"(a0), "r"(a1), "r"(a2), "r"(a3), "r"(b0), "r"(b1));
}

__global__ __launch_bounds__(NT)
void wta_attn10_kernel(const float* __restrict__ q,
                       const float* __restrict__ k,
                       const float* __restrict__ v,
                       float* __restrict__ out,
                       int write_out, int write_attn, long long attn_off)
{
    __shared__ float ks[2][BK][KPAD];          // 34.8 KB: two resident tf32 k tiles
    __shared__ float tilemax[BQ][NTILES];      //  8  KB
    __shared__ float rs[2][BQ];
    __shared__ float rowsum[BQ];
    __shared__ float pval[BQ];
    __shared__ int   widx[BQ];

    const int b    = blockIdx.y;
    const int q0   = blockIdx.x * BQ;
    const int tid  = threadIdx.x;
    const int w    = tid >> 5;
    const int lane = tid & 31;
    const int wg   = w & 3;        // row group
    const int half = w >> 2;       // k half
    const int l4   = lane >> 2;
    const int lm   = lane & 3;

    const float* qb = q + ((size_t)b * LQ + q0) * DH;
    const float* kb = k + (size_t)b * LK * DH;

    const int r0 = wg * 16 + l4;
    const int r1 = r0 + 8;

    // ---- A fragments (q): tf32 once, resident in regs ----
    unsigned Af[8][4];
    #pragma unroll
    for (int s = 0; s < 8; s++) {
        Af[s][0] = cvt_tf32(qb[(size_t)r0 * DH + s * 8 + lm]);
        Af[s][1] = cvt_tf32(qb[(size_t)r1 * DH + s * 8 + lm]);
        Af[s][2] = cvt_tf32(qb[(size_t)r0 * DH + s * 8 + lm + 4]);
        Af[s][3] = cvt_tf32(qb[(size_t)r1 * DH + s * 8 + lm + 4]);
    }

    const float C = 0.18033688011112042f;   // 0.125 * log2(e)
    float sum0 = 0.0f, sum1 = 0.0f;

    float4* az = 0;
    if (write_attn)
        az = (float4*)(out + attn_off + ((size_t)b * LQ + q0) * LK);

    // ---- register-staged prefetch: this thread's 8 float4 of the tile pair ----
    float4 pf[8];
    #pragma unroll
    for (int i = 0; i < 8; i++) {
        int fi  = tid + i * NT;
        int buf = fi >> 10;
        int wi  = fi & 1023;
        pf[i] = ((const float4*)(kb + (size_t)(0 + buf * HTILES) * BK * DH))[wi];
    }

    // ================= mainloop: 16 iterations, 2 tiles resident =================
    for (int it = 0; it < HTILES; it++) {
        __syncthreads();           // previous iteration's smem reads complete

        // ---- STS staged regs (cvt to tf32 at store time) ----
        #pragma unroll
        for (int i = 0; i < 8; i++) {
            int fi   = tid + i * NT;
            int buf  = fi >> 10;
            int wi   = fi & 1023;
            int krow = wi >> 4;
            int c4   = wi & 15;
            ks[buf][krow][c4 * 4 + 0] = __uint_as_float(cvt_tf32(pf[i].x));
            ks[buf][krow][c4 * 4 + 1] = __uint_as_float(cvt_tf32(pf[i].y));
            ks[buf][krow][c4 * 4 + 2] = __uint_as_float(cvt_tf32(pf[i].z));
            ks[buf][krow][c4 * 4 + 3] = __uint_as_float(cvt_tf32(pf[i].w));
        }

        // ---- issue next iteration's LDGs (latency hidden behind compute) ----
        if (it + 1 < HTILES) {
            #pragma unroll
            for (int i = 0; i < 8; i++) {
                int fi  = tid + i * NT;
                int buf = fi >> 10;
                int wi  = fi & 1023;
                pf[i] = ((const float4*)(kb + (size_t)(it + 1 + buf * HTILES) * BK * DH))[wi];
            }
        }

        // ---- interleaved zero-fill: chunks for tiles it and it+16 ----
        if (write_attn) {
            #pragma unroll
            for (int j = 0; j < 8; j++) {
                int fi  = tid + j * NT;
                int buf = fi >> 10;
                int wi  = fi & 1023;
                az[(size_t)(it + buf * HTILES) * (BQ * BK / 4) + wi] =
                    make_float4(0.f, 0.f, 0.f, 0.f);
            }
        }
        __syncthreads();

        const int t = it + half * HTILES;

        float acc[8][4];
        #pragma unroll
        for (int n = 0; n < 8; n++)
            #pragma unroll
            for (int c = 0; c < 4; c++) acc[n][c] = 0.0f;

        #pragma unroll
        for (int n = 0; n < 8; n++) {
            #pragma unroll
            for (int s = 0; s < 8; s++) {
                unsigned b0 = __float_as_uint(ks[half][n * 8 + l4][s * 8 + lm]);
                unsigned b1 = __float_as_uint(ks[half][n * 8 + l4][s * 8 + lm + 4]);
                mma_tf32(acc[n], Af[s][0], Af[s][1], Af[s][2], Af[s][3], b0, b1);
            }
        }

        float tm0 = -1e30f, tm1 = -1e30f;
        #pragma unroll
        for (int n = 0; n < 8; n++) {
            tm0 = fmaxf(tm0, fmaxf(acc[n][0], acc[n][1]));
            tm1 = fmaxf(tm1, fmaxf(acc[n][2], acc[n][3]));
            sum0 += ex2a(acc[n][0] * C) + ex2a(acc[n][1] * C);
            sum1 += ex2a(acc[n][2] * C) + ex2a(acc[n][3] * C);
        }
        #pragma unroll
        for (int off = 1; off <= 2; off <<= 1) {
            tm0 = fmaxf(tm0, __shfl_xor_sync(0xffffffffu, tm0, off));
            tm1 = fmaxf(tm1, __shfl_xor_sync(0xffffffffu, tm1, off));
        }
        if (lm == 0) { tilemax[r0][t] = tm0; tilemax[r1][t] = tm1; }
    }

    // partial row sums per half
    #pragma unroll
    for (int off = 1; off <= 2; off <<= 1) {
        sum0 += __shfl_xor_sync(0xffffffffu, sum0, off);
        sum1 += __shfl_xor_sync(0xffffffffu, sum1, off);
    }
    if (lm == 0) { rs[half][r0] = sum0; rs[half][r1] = sum1; }
    __syncthreads();

    if (tid < BQ) rowsum[tid] = rs[0][tid] + rs[1][tid];
    __syncthreads();

    // ================= repair: one warp per row, warp-uniform branches =================
    #pragma unroll 1
    for (int rr8 = 0; rr8 < BQ / 8; rr8++) {
        const int r = w * 8 + rr8;

        const float tmv = tilemax[r][lane];      // 32 lanes = 32 tiles
        float best = tmv;
        #pragma unroll
        for (int off = 16; off > 0; off >>= 1)
            best = fmaxf(best, __shfl_xor_sync(0xffffffffu, best, off));
        const float thr = best - REPAIR_EPS;

        const float4 qv = *(const float4*)(qb + (size_t)r * DH + (lane & 15) * 4);

        float bm = -1e30f;
        int   bi = 0;
        #pragma unroll 1
        for (int t = 0; t < NTILES; t++) {
            if (__shfl_sync(0xffffffffu, tmv, t) < thr) continue;   // warp-uniform
            const float* kt = kb + (size_t)t * BK * DH;
            #pragma unroll 4
            for (int rr = 0; rr < 32; rr++) {
                const int col = rr * 2 + (lane >> 4);
                const float4 kv = *(const float4*)(kt + (size_t)col * DH + (lane & 15) * 4);
                float p = fmaf(qv.x, kv.x, fmaf(qv.y, kv.y,
                          fmaf(qv.z, kv.z, qv.w * kv.w)));
                p += __shfl_xor_sync(0xffffffffu, p, 8, 16);
                p += __shfl_xor_sync(0xffffffffu, p, 4, 16);
                p += __shfl_xor_sync(0xffffffffu, p, 2, 16);
                p += __shfl_xor_sync(0xffffffffu, p, 1, 16);
                if (p > bm) { bm = p; bi = t * BK + col; }  // strict > : lowest t/col kept
            }
        }
        #pragma unroll
        for (int off = 16; off > 0; off >>= 1) {
            float om = __shfl_xor_sync(0xffffffffu, bm, off);
            int   oi = __shfl_xor_sync(0xffffffffu, bi, off);
            if (om > bm || (om == bm && oi < bi)) { bm = om; bi = oi; }
        }
        if (lane == 0) {
            float p = ex2a(bm * C) / rowsum[r];
            pval[r] = p;
            widx[r] = bi;
            if (write_attn)
                out[attn_off + ((size_t)b * LQ + q0 + r) * LK + bi] = p;
        }
    }
    __syncthreads();

    // ================= dense output =================
    if (write_out) {
        #pragma unroll
        for (int i = tid; i < BQ * (DH / 4); i += NT) {
            const int r = i >> 4;
            const int c = i & 15;
            const float p = pval[r];
            const float4 vv = *(const float4*)(v + ((size_t)b * LK + widx[r]) * DH + c * 4);
            float4 o;
            o.x = p * vv.x; o.y = p * vv.y; o.z = p * vv.z; o.w = p * vv.w;
            *(float4*)(out + ((size_t)b * LQ + q0 + r) * DH + c * 4) = o;
        }
    }
}

extern "C" void kernel_launch(void* const* d_in, const int* in_sizes, int n_in,
                              void* d_out, int out_size)
{
    const float* q = (const float*)d_in[0];
    const float* k = (const float*)d_in[1];
    const float* v = (const float*)d_in[2];
    float* out = (float*)d_out;

    int wout = 0, wattn = 0;
    long long aoff = 0;
    size_t osz = (size_t)out_size;
    if (osz == OUT_ELEMS + ATTN_ELEMS) { wout = 1; wattn = 1; aoff = (long long)OUT_ELEMS; }
    else if (osz == ATTN_ELEMS)        { wattn = 1; aoff = 0; }
    else                               { wout = 1; }

    dim3 grid(LQ / BQ, BATCH);
    wta_attn10_kernel<<<grid, NT>>>(q, k, v, out, wout, wattn, aoff);
}

// round 11
// speedup vs baseline: 1.2868x; 1.2388x over previous
#include <cuda_runtime.h>
#include <stdint.h>

// Problem constants
#define BATCH 16
#define LQ 2048
#define LK 2048
#define DH 64

// Block = 64 q-rows x full LK, k-tiles of 64. 256 threads (8 warps).
// ALL warps compute the same tile: wg = w&3 -> rows wg*16..+16,
// nh = w>>2 -> B-rows (attn cols) nh*32..+32. Double-buffered cp.async pipeline.
#define BQ 64
#define BK 64
#define NT 256
#define NTILES (LK / BK)     // 32
#define KPAD 68              // fp32 k row stride; row = 272 B (16B-aligned for cp.async)

#define OUT_ELEMS  ((size_t)BATCH * LQ * DH)   // 2,097,152
#define ATTN_ELEMS ((size_t)BATCH * LQ * LK)   // 67,108,864

#define REPAIR_EPS 0.2f

__device__ __forceinline__ float ex2a(float x) {
    float r; asm("ex2.approx.ftz.f32 %0, %1;" : "=f"(r) : "f"(x)); return r;
}
__device__ __forceinline__ unsigned cvt_tf32(float x) {
    unsigned r; asm("cvt.rna.tf32.f32 %0, %1;" : "=r"(r) : "f"(x)); return r;
}
__device__ __forceinline__ void mma_tf32(float c[4],
                                         unsigned a0, unsigned a1, unsigned a2, unsigned a3,
                                         unsigned b0, unsigned b1) {
    asm volatile("mma.sync.aligned.m16n8k8.row.col.f32.tf32.tf32.f32 "
                 "{%0,%1,%2,%3}, {%4,%5,%6,%7}, {%8,%9}, {%0,%1,%2,%3};"
                 : "+f"(c[0]), "+f"(c[1]), "+f"(c[2]), "+f"(c[3])
                 : "r"(a0), "r"(a1), "r"(a2), "r"(a3), "r"(b0), "r"(b1));
}
__device__ __forceinline__ void cp_async16(uint32_t dst_smem, const void* src) {
    asm volatile("cp.async.cg.shared.global [%0], [%1], 16;"
                 :: "r"(dst_smem), "l"(src) : "memory");
}
#define CP_COMMIT() asm volatile("cp.async.commit_group;" ::: "memory")
#define CP_WAIT0()  asm volatile("cp.async.wait_group 0;" ::: "memory")

__global__ __launch_bounds__(NT)
void wta_attn11_kernel(const float* __restrict__ q,
                       const float* __restrict__ k,
                       const float* __restrict__ v,
                       float* __restrict__ out,
                       int write_out, int write_attn, long long attn_off)
{
    __shared__ float ks[2][BK][KPAD];          // 34.8 KB: double-buffered fp32 k tiles
    __shared__ float tilemax[BQ][NTILES];      //  8  KB (combined)
    __shared__ float tmstage[2][2][BQ];        //  1  KB (iter-parity, nh, row)
    __shared__ float rs[2][BQ];
    __shared__ float rowsum[BQ];
    __shared__ float pval[BQ];
    __shared__ int   widx[BQ];

    const int b    = blockIdx.y;
    const int q0   = blockIdx.x * BQ;
    const int tid  = threadIdx.x;
    const int w    = tid >> 5;
    const int lane = tid & 31;
    const int wg   = w & 3;        // row group
    const int nh   = w >> 2;       // col half
    const int l4   = lane >> 2;
    const int lm   = lane & 3;

    const float* qb = q + ((size_t)b * LQ + q0) * DH;
    const float* kb = k + (size_t)b * LK * DH;

    const int r0 = wg * 16 + l4;
    const int r1 = r0 + 8;

    // per-thread cp.async slots: 4 x 16B per tile
    const int krw = (tid * 4) >> 6;            // fi>>4 with fi=tid*? -> use fi mapping below

    // ---- A fragments (q): tf32 once, resident in regs ----
    unsigned Af[8][4];
    #pragma unroll
    for (int s = 0; s < 8; s++) {
        Af[s][0] = cvt_tf32(qb[(size_t)r0 * DH + s * 8 + lm]);
        Af[s][1] = cvt_tf32(qb[(size_t)r1 * DH + s * 8 + lm]);
        Af[s][2] = cvt_tf32(qb[(size_t)r0 * DH + s * 8 + lm + 4]);
        Af[s][3] = cvt_tf32(qb[(size_t)r1 * DH + s * 8 + lm + 4]);
    }
    (void)krw;

    const float C = 0.18033688011112042f;   // 0.125 * log2(e)
    float sum0 = 0.0f, sum1 = 0.0f;

    float4* az = 0;
    if (write_attn)
        az = (float4*)(out + attn_off + ((size_t)b * LQ + q0) * LK);

    // smem byte addresses of this thread's 4 cp.async destinations per buffer
    uint32_t dst[2][4];
    #pragma unroll
    for (int i = 0; i < 4; i++) {
        int fi   = tid + i * NT;               // 0..1023 (16B chunks)
        int kr   = fi >> 4;
        int c4   = fi & 15;
        dst[0][i] = (uint32_t)__cvta_generic_to_shared(&ks[0][kr][c4 * 4]);
        dst[1][i] = (uint32_t)__cvta_generic_to_shared(&ks[1][kr][c4 * 4]);
    }

    // ---- prologue: fill buffer 0 with tile 0 ----
    #pragma unroll
    for (int i = 0; i < 4; i++) {
        int fi = tid + i * NT;
        cp_async16(dst[0][i], kb + (size_t)fi * 4);
    }
    CP_COMMIT();
    CP_WAIT0();
    __syncthreads();

    // ================= mainloop: double-buffered pipeline =================
    for (int t = 0; t < NTILES; t++) {
        const int cur = t & 1;

        // issue next tile's copies into the other buffer (overlaps compute)
        if (t + 1 < NTILES) {
            const float* src = kb + (size_t)(t + 1) * BK * DH;
            #pragma unroll
            for (int i = 0; i < 4; i++) {
                int fi = tid + i * NT;
                cp_async16(dst[cur ^ 1][i], src + (size_t)fi * 4);
            }
            CP_COMMIT();
        }

        // combine tilemax for tile t-1 (staged last iteration, sync'd since)
        if (t > 0 && tid < BQ)
            tilemax[tid][t - 1] = fmaxf(tmstage[cur ^ 1][0][tid],
                                        tmstage[cur ^ 1][1][tid]);

        // ---- compute: 16 rows x 32 cols per warp on buffer cur ----
        float acc[4][4];
        #pragma unroll
        for (int nc = 0; nc < 4; nc++)
            #pragma unroll
            for (int c = 0; c < 4; c++) acc[nc][c] = 0.0f;

        #pragma unroll
        for (int nc = 0; nc < 4; nc++) {
            const float* rp = &ks[cur][nh * 32 + nc * 8 + l4][0];
            #pragma unroll
            for (int s = 0; s < 8; s++) {
                unsigned b0 = cvt_tf32(rp[s * 8 + lm]);
                unsigned b1 = cvt_tf32(rp[s * 8 + lm + 4]);
                mma_tf32(acc[nc], Af[s][0], Af[s][1], Af[s][2], Af[s][3], b0, b1);
            }
        }

        // ---- epilogue: max + exp-sum over this warp's 32 cols ----
        float tm0 = -1e30f, tm1 = -1e30f;
        #pragma unroll
        for (int nc = 0; nc < 4; nc++) {
            tm0 = fmaxf(tm0, fmaxf(acc[nc][0], acc[nc][1]));
            tm1 = fmaxf(tm1, fmaxf(acc[nc][2], acc[nc][3]));
            sum0 += ex2a(acc[nc][0] * C) + ex2a(acc[nc][1] * C);
            sum1 += ex2a(acc[nc][2] * C) + ex2a(acc[nc][3] * C);
        }
        #pragma unroll
        for (int off = 1; off <= 2; off <<= 1) {
            tm0 = fmaxf(tm0, __shfl_xor_sync(0xffffffffu, tm0, off));
            tm1 = fmaxf(tm1, __shfl_xor_sync(0xffffffffu, tm1, off));
        }
        if (lm == 0) { tmstage[cur][nh][r0] = tm0; tmstage[cur][nh][r1] = tm1; }

        // ---- interleaved zero-fill of this tile's attn chunk ----
        if (write_attn) {
            float4* azc = az + (size_t)t * (BQ * BK / 4);
            #pragma unroll
            for (int j = 0; j < 4; j++)
                azc[tid + j * NT] = make_float4(0.f, 0.f, 0.f, 0.f);
        }

        if (t + 1 < NTILES) CP_WAIT0();   // next buffer filled
        __syncthreads();
    }
    // combine last tile's max
    if (tid < BQ)
        tilemax[tid][NTILES - 1] = fmaxf(tmstage[(NTILES - 1) & 1][0][tid],
                                         tmstage[(NTILES - 1) & 1][1][tid]);

    // partial row sums per col-half
    #pragma unroll
    for (int off = 1; off <= 2; off <<= 1) {
        sum0 += __shfl_xor_sync(0xffffffffu, sum0, off);
        sum1 += __shfl_xor_sync(0xffffffffu, sum1, off);
    }
    if (lm == 0) { rs[nh][r0] = sum0; rs[nh][r1] = sum1; }
    __syncthreads();

    if (tid < BQ) rowsum[tid] = rs[0][tid] + rs[1][tid];
    __syncthreads();

    // ================= repair: one warp per row, warp-uniform branches =================
    #pragma unroll 1
    for (int rr8 = 0; rr8 < BQ / 8; rr8++) {
        const int r = w * 8 + rr8;

        const float tmv = tilemax[r][lane];      // 32 lanes = 32 tiles
        float best = tmv;
        #pragma unroll
        for (int off = 16; off > 0; off >>= 1)
            best = fmaxf(best, __shfl_xor_sync(0xffffffffu, best, off));
        const float thr = best - REPAIR_EPS;

        const float4 qv = *(const float4*)(qb + (size_t)r * DH + (lane & 15) * 4);

        float bm = -1e30f;
        int   bi = 0;
        #pragma unroll 1
        for (int t = 0; t < NTILES; t++) {
            if (__shfl_sync(0xffffffffu, tmv, t) < thr) continue;   // warp-uniform
            const float* kt = kb + (size_t)t * BK * DH;
            #pragma unroll 4
            for (int rr = 0; rr < 32; rr++) {
                const int col = rr * 2 + (lane >> 4);
                const float4 kv = *(const float4*)(kt + (size_t)col * DH + (lane & 15) * 4);
                float p = fmaf(qv.x, kv.x, fmaf(qv.y, kv.y,
                          fmaf(qv.z, kv.z, qv.w * kv.w)));
                p += __shfl_xor_sync(0xffffffffu, p, 8, 16);
                p += __shfl_xor_sync(0xffffffffu, p, 4, 16);
                p += __shfl_xor_sync(0xffffffffu, p, 2, 16);
                p += __shfl_xor_sync(0xffffffffu, p, 1, 16);
                if (p > bm) { bm = p; bi = t * BK + col; }  // strict > : lowest t/col kept
            }
        }
        #pragma unroll
        for (int off = 16; off > 0; off >>= 1) {
            float om = __shfl_xor_sync(0xffffffffu, bm, off);
            int   oi = __shfl_xor_sync(0xffffffffu, bi, off);
            if (om > bm || (om == bm && oi < bi)) { bm = om; bi = oi; }
        }
        if (lane == 0) {
            float p = ex2a(bm * C) / rowsum[r];
            pval[r] = p;
            widx[r] = bi;
            if (write_attn)
                out[attn_off + ((size_t)b * LQ + q0 + r) * LK + bi] = p;
        }
    }
    __syncthreads();

    // ================= dense output =================
    if (write_out) {
        #pragma unroll
        for (int i = tid; i < BQ * (DH / 4); i += NT) {
            const int r = i >> 4;
            const int c = i & 15;
            const float p = pval[r];
            const float4 vv = *(const float4*)(v + ((size_t)b * LK + widx[r]) * DH + c * 4);
            float4 o;
            o.x = p * vv.x; o.y = p * vv.y; o.z = p * vv.z; o.w = p * vv.w;
            *(float4*)(out + ((size_t)b * LQ + q0 + r) * DH + c * 4) = o;
        }
    }
}

extern "C" void kernel_launch(void* const* d_in, const int* in_sizes, int n_in,
                              void* d_out, int out_size)
{
    const float* q = (const float*)d_in[0];
    const float* k = (const float*)d_in[1];
    const float* v = (const float*)d_in[2];
    float* out = (float*)d_out;

    int wout = 0, wattn = 0;
    long long aoff = 0;
    size_t osz = (size_t)out_size;
    if (osz == OUT_ELEMS + ATTN_ELEMS) { wout = 1; wattn = 1; aoff = (long long)OUT_ELEMS; }
    else if (osz == ATTN_ELEMS)        { wattn = 1; aoff = 0; }
    else                               { wout = 1; }

    dim3 grid(LQ / BQ, BATCH);
    wta_attn11_kernel<<<grid, NT>>>(q, k, v, out, wout, wattn, aoff);
}

// round 12
// speedup vs baseline: 1.3679x; 1.0630x over previous
#include <cuda_runtime.h>
#include <stdint.h>

// Problem constants
#define BATCH 16
#define LQ 2048
#define LK 2048
#define DH 64

// Block = 64 q-rows x full LK, k-tiles of 64. 256 threads (8 warps).
// All warps compute the same tile: wg = w&3 -> rows wg*16..+16,
// nh = w>>2 -> attn cols nh*32..+32. Double-buffered cp.async pipeline.
// B operands: raw fp32 bits fed to tf32 mma (HW truncation; zero-mean score err ~2e-3).
#define BQ 64
#define BK 64
#define NT 256
#define NTILES (LK / BK)     // 32
#define KPAD 68              // fp32 k row stride; 272 B rows, 16B-aligned chunks

#define OUT_ELEMS  ((size_t)BATCH * LQ * DH)   // 2,097,152
#define ATTN_ELEMS ((size_t)BATCH * LQ * LK)   // 67,108,864

#define REPAIR_EPS 0.2f

__device__ __forceinline__ float ex2a(float x) {
    float r; asm("ex2.approx.ftz.f32 %0, %1;" : "=f"(r) : "f"(x)); return r;
}
__device__ __forceinline__ unsigned cvt_tf32(float x) {
    unsigned r; asm("cvt.rna.tf32.f32 %0, %1;" : "=r"(r) : "f"(x)); return r;
}
__device__ __forceinline__ void mma_tf32(float c[4],
                                         unsigned a0, unsigned a1, unsigned a2, unsigned a3,
                                         unsigned b0, unsigned b1) {
    asm volatile("mma.sync.aligned.m16n8k8.row.col.f32.tf32.tf32.f32 "
                 "{%0,%1,%2,%3}, {%4,%5,%6,%7}, {%8,%9}, {%0,%1,%2,%3};"
                 : "+f"(c[0]), "+f"(c[1]), "+f"(c[2]), "+f"(c[3])
                 : "r"(a0), "r"(a1), "r"(a2), "r"(a3), "r"(b0), "r"(b1));
}
__device__ __forceinline__ void cp_async16(uint32_t dst_smem, const void* src) {
    asm volatile("cp.async.cg.shared.global [%0], [%1], 16;"
                 :: "r"(dst_smem), "l"(src) : "memory");
}
#define CP_COMMIT() asm volatile("cp.async.commit_group;" ::: "memory")
#define CP_WAIT0()  asm volatile("cp.async.wait_group 0;" ::: "memory")

__global__ __launch_bounds__(NT)
void wta_attn12_kernel(const float* __restrict__ q,
                       const float* __restrict__ k,
                       const float* __restrict__ v,
                       float* __restrict__ out,
                       int write_out, int write_attn, long long attn_off)
{
    __shared__ float ks[2][BK][KPAD];          // 34.8 KB: double-buffered fp32 k tiles
    __shared__ float tilemax[BQ][NTILES];      //  8  KB
    __shared__ float tmstage[2][2][BQ];        //  1  KB (iter-parity, nh, row)
    __shared__ float rs[2][BQ];
    __shared__ float rowsum[BQ];
    __shared__ float pval[BQ];
    __shared__ int   widx[BQ];

    const int b    = blockIdx.y;
    const int q0   = blockIdx.x * BQ;
    const int tid  = threadIdx.x;
    const int w    = tid >> 5;
    const int lane = tid & 31;
    const int wg   = w & 3;        // row group
    const int nh   = w >> 2;       // col half
    const int l4   = lane >> 2;
    const int lm   = lane & 3;

    const float* qb = q + ((size_t)b * LQ + q0) * DH;
    const float* kb = k + (size_t)b * LK * DH;

    const int r0 = wg * 16 + l4;
    const int r1 = r0 + 8;

    // ---- A fragments (q): rna tf32 once, resident in regs ----
    unsigned Af[8][4];
    #pragma unroll
    for (int s = 0; s < 8; s++) {
        Af[s][0] = cvt_tf32(qb[(size_t)r0 * DH + s * 8 + lm]);
        Af[s][1] = cvt_tf32(qb[(size_t)r1 * DH + s * 8 + lm]);
        Af[s][2] = cvt_tf32(qb[(size_t)r0 * DH + s * 8 + lm + 4]);
        Af[s][3] = cvt_tf32(qb[(size_t)r1 * DH + s * 8 + lm + 4]);
    }

    const float C = 0.18033688011112042f;   // 0.125 * log2(e)
    float sum0 = 0.0f, sum1 = 0.0f;

    float4* az = 0;
    if (write_attn)
        az = (float4*)(out + attn_off + ((size_t)b * LQ + q0) * LK);

    // smem byte addresses of this thread's 4 cp.async destinations per buffer
    uint32_t dst[2][4];
    #pragma unroll
    for (int i = 0; i < 4; i++) {
        int fi   = tid + i * NT;               // 0..1023 (16B chunks)
        int kr   = fi >> 4;
        int c4   = fi & 15;
        dst[0][i] = (uint32_t)__cvta_generic_to_shared(&ks[0][kr][c4 * 4]);
        dst[1][i] = (uint32_t)__cvta_generic_to_shared(&ks[1][kr][c4 * 4]);
    }

    // ---- prologue: fill buffer 0 with tile 0 ----
    #pragma unroll
    for (int i = 0; i < 4; i++) {
        int fi = tid + i * NT;
        cp_async16(dst[0][i], kb + (size_t)fi * 4);
    }
    CP_COMMIT();
    CP_WAIT0();
    __syncthreads();

    // ================= mainloop: double-buffered pipeline =================
    for (int t = 0; t < NTILES; t++) {
        const int cur = t & 1;

        // issue next tile's copies into the other buffer (overlaps compute)
        if (t + 1 < NTILES) {
            const float* src = kb + (size_t)(t + 1) * BK * DH;
            #pragma unroll
            for (int i = 0; i < 4; i++) {
                int fi = tid + i * NT;
                cp_async16(dst[cur ^ 1][i], src + (size_t)fi * 4);
            }
            CP_COMMIT();
        }

        // combine tilemax for tile t-1 (staged last iteration, sync'd since)
        if (t > 0 && tid < BQ)
            tilemax[tid][t - 1] = fmaxf(tmstage[cur ^ 1][0][tid],
                                        tmstage[cur ^ 1][1][tid]);

        // ---- compute: 16 rows x 32 cols per warp on buffer cur ----
        float acc[4][4];
        #pragma unroll
        for (int nc = 0; nc < 4; nc++)
            #pragma unroll
            for (int c = 0; c < 4; c++) acc[nc][c] = 0.0f;

        #pragma unroll
        for (int nc = 0; nc < 4; nc++) {
            const float* rp = &ks[cur][nh * 32 + nc * 8 + l4][0];
            #pragma unroll
            for (int s = 0; s < 8; s++) {
                // raw fp32 bits as tf32 operands (HW truncation, zero-mean err)
                unsigned b0 = __float_as_uint(rp[s * 8 + lm]);
                unsigned b1 = __float_as_uint(rp[s * 8 + lm + 4]);
                mma_tf32(acc[nc], Af[s][0], Af[s][1], Af[s][2], Af[s][3], b0, b1);
            }
        }

        // ---- epilogue: max + exp-sum over this warp's 32 cols ----
        float tm0 = -1e30f, tm1 = -1e30f;
        #pragma unroll
        for (int nc = 0; nc < 4; nc++) {
            tm0 = fmaxf(tm0, fmaxf(acc[nc][0], acc[nc][1]));
            tm1 = fmaxf(tm1, fmaxf(acc[nc][2], acc[nc][3]));
            sum0 += ex2a(acc[nc][0] * C) + ex2a(acc[nc][1] * C);
            sum1 += ex2a(acc[nc][2] * C) + ex2a(acc[nc][3] * C);
        }
        #pragma unroll
        for (int off = 1; off <= 2; off <<= 1) {
            tm0 = fmaxf(tm0, __shfl_xor_sync(0xffffffffu, tm0, off));
            tm1 = fmaxf(tm1, __shfl_xor_sync(0xffffffffu, tm1, off));
        }
        if (lm == 0) { tmstage[cur][nh][r0] = tm0; tmstage[cur][nh][r1] = tm1; }

        // ---- interleaved zero-fill of this tile's attn chunk ----
        if (write_attn) {
            float4* azc = az + (size_t)t * (BQ * BK / 4);
            #pragma unroll
            for (int j = 0; j < 4; j++)
                azc[tid + j * NT] = make_float4(0.f, 0.f, 0.f, 0.f);
        }

        if (t + 1 < NTILES) CP_WAIT0();   // next buffer filled
        __syncthreads();
    }
    // combine last tile's max
    if (tid < BQ)
        tilemax[tid][NTILES - 1] = fmaxf(tmstage[(NTILES - 1) & 1][0][tid],
                                         tmstage[(NTILES - 1) & 1][1][tid]);

    // partial row sums per col-half
    #pragma unroll
    for (int off = 1; off <= 2; off <<= 1) {
        sum0 += __shfl_xor_sync(0xffffffffu, sum0, off);
        sum1 += __shfl_xor_sync(0xffffffffu, sum1, off);
    }
    if (lm == 0) { rs[nh][r0] = sum0; rs[nh][r1] = sum1; }
    __syncthreads();

    if (tid < BQ) rowsum[tid] = rs[0][tid] + rs[1][tid];
    __syncthreads();

    // ================= repair: one warp per row, warp-uniform branches =================
    #pragma unroll 1
    for (int rr8 = 0; rr8 < BQ / 8; rr8++) {
        const int r = w * 8 + rr8;

        const float tmv = tilemax[r][lane];      // 32 lanes = 32 tiles
        float best = tmv;
        #pragma unroll
        for (int off = 16; off > 0; off >>= 1)
            best = fmaxf(best, __shfl_xor_sync(0xffffffffu, best, off));
        const float thr = best - REPAIR_EPS;

        const float4 qv = *(const float4*)(qb + (size_t)r * DH + (lane & 15) * 4);

        float bm = -1e30f;
        int   bi = 0;
        #pragma unroll 1
        for (int t = 0; t < NTILES; t++) {
            if (__shfl_sync(0xffffffffu, tmv, t) < thr) continue;   // warp-uniform
            const float* kt = kb + (size_t)t * BK * DH;
            #pragma unroll 4
            for (int rr = 0; rr < 32; rr++) {
                const int col = rr * 2 + (lane >> 4);
                const float4 kv = *(const float4*)(kt + (size_t)col * DH + (lane & 15) * 4);
                float p = fmaf(qv.x, kv.x, fmaf(qv.y, kv.y,
                          fmaf(qv.z, kv.z, qv.w * kv.w)));
                p += __shfl_xor_sync(0xffffffffu, p, 8, 16);
                p += __shfl_xor_sync(0xffffffffu, p, 4, 16);
                p += __shfl_xor_sync(0xffffffffu, p, 2, 16);
                p += __shfl_xor_sync(0xffffffffu, p, 1, 16);
                if (p > bm) { bm = p; bi = t * BK + col; }  // strict > : lowest t/col kept
            }
        }
        #pragma unroll
        for (int off = 16; off > 0; off >>= 1) {
            float om = __shfl_xor_sync(0xffffffffu, bm, off);
            int   oi = __shfl_xor_sync(0xffffffffu, bi, off);
            if (om > bm || (om == bm && oi < bi)) { bm = om; bi = oi; }
        }
        if (lane == 0) {
            float p = ex2a(bm * C) / rowsum[r];
            pval[r] = p;
            widx[r] = bi;
            if (write_attn)
                out[attn_off + ((size_t)b * LQ + q0 + r) * LK + bi] = p;
        }
    }
    __syncthreads();

    // ================= dense output =================
    if (write_out) {
        #pragma unroll
        for (int i = tid; i < BQ * (DH / 4); i += NT) {
            const int r = i >> 4;
            const int c = i & 15;
            const float p = pval[r];
            const float4 vv = *(const float4*)(v + ((size_t)b * LK + widx[r]) * DH + c * 4);
            float4 o;
            o.x = p * vv.x; o.y = p * vv.y; o.z = p * vv.z; o.w = p * vv.w;
            *(float4*)(out + ((size_t)b * LQ + q0 + r) * DH + c * 4) = o;
        }
    }
}

extern "C" void kernel_launch(void* const* d_in, const int* in_sizes, int n_in,
                              void* d_out, int out_size)
{
    const float* q = (const float*)d_in[0];
    const float* k = (const float*)d_in[1];
    const float* v = (const float*)d_in[2];
    float* out = (float*)d_out;

    int wout = 0, wattn = 0;
    long long aoff = 0;
    size_t osz = (size_t)out_size;
    if (osz == OUT_ELEMS + ATTN_ELEMS) { wout = 1; wattn = 1; aoff = (long long)OUT_ELEMS; }
    else if (osz == ATTN_ELEMS)        { wattn = 1; aoff = 0; }
    else                               { wout = 1; }

    dim3 grid(LQ / BQ, BATCH);
    wta_attn12_kernel<<<grid, NT>>>(q, k, v, out, wout, wattn, aoff);
}

// round 13
// speedup vs baseline: 1.4706x; 1.0751x over previous
#include <cuda_runtime.h>
#include <stdint.h>

// Problem constants
#define BATCH 16
#define LQ 2048
#define LK 2048
#define DH 64

// Block = 64 q-rows x full LK, k-tiles of 64. 256 threads (8 warps).
// All warps compute the same tile: wg = w&3 -> rows wg*16..+16,
// nh = w>>2 -> attn cols nh*32..+32. Double-buffered cp.async pipeline.
// B operands: raw fp32 bits as tf32 (HW truncation); the one-sided truncation
// bias E[delta]=2^-11*ln2 is cancelled by scaling A with (1+3.38e-4).
// K-index permutation: B thread (l4,lm) reads physical words s*8+2lm,+1 (one
// LDS.64, conflict-free at stride 72); A fragments use the matching indices.
#define BQ 64
#define BK 64
#define NT 256
#define NTILES (LK / BK)     // 32
#define KPAD 72              // fp32 k row stride: 288 B rows, LDS.64 conflict-free

#define OUT_ELEMS  ((size_t)BATCH * LQ * DH)   // 2,097,152
#define ATTN_ELEMS ((size_t)BATCH * LQ * LK)   // 67,108,864

#define REPAIR_EPS 0.2f
#define TRUNC_CORR 1.000338f   // 1 + 2^-11 * ln2

__device__ __forceinline__ float ex2a(float x) {
    float r; asm("ex2.approx.ftz.f32 %0, %1;" : "=f"(r) : "f"(x)); return r;
}
__device__ __forceinline__ unsigned cvt_tf32(float x) {
    unsigned r; asm("cvt.rna.tf32.f32 %0, %1;" : "=r"(r) : "f"(x)); return r;
}
__device__ __forceinline__ void mma_tf32(float c[4],
                                         unsigned a0, unsigned a1, unsigned a2, unsigned a3,
                                         unsigned b0, unsigned b1) {
    asm volatile("mma.sync.aligned.m16n8k8.row.col.f32.tf32.tf32.f32 "
                 "{%0,%1,%2,%3}, {%4,%5,%6,%7}, {%8,%9}, {%0,%1,%2,%3};"
                 : "+f"(c[0]), "+f"(c[1]), "+f"(c[2]), "+f"(c[3])
                 : "r"(a0), "r"(a1), "r"(a2), "r"(a3), "r"(b0), "r"(b1));
}
__device__ __forceinline__ void cp_async16(uint32_t dst_smem, const void* src) {
    asm volatile("cp.async.cg.shared.global [%0], [%1], 16;"
                 :: "r"(dst_smem), "l"(src) : "memory");
}
#define CP_COMMIT() asm volatile("cp.async.commit_group;" ::: "memory")
#define CP_WAIT0()  asm volatile("cp.async.wait_group 0;" ::: "memory")

__global__ __launch_bounds__(NT)
void wta_attn13_kernel(const float* __restrict__ q,
                       const float* __restrict__ k,
                       const float* __restrict__ v,
                       float* __restrict__ out,
                       int write_out, int write_attn, long long attn_off)
{
    __shared__ float ks[2][BK][KPAD];          // 36.9 KB: double-buffered fp32 k tiles
    __shared__ float tilemax[BQ][NTILES];      //  8  KB
    __shared__ float tmstage[2][2][BQ];        //  1  KB (iter-parity, nh, row)
    __shared__ float rs[2][BQ];
    __shared__ float rowsum[BQ];
    __shared__ float pval[BQ];
    __shared__ int   widx[BQ];

    const int b    = blockIdx.y;
    const int q0   = blockIdx.x * BQ;
    const int tid  = threadIdx.x;
    const int w    = tid >> 5;
    const int lane = tid & 31;
    const int wg   = w & 3;        // row group
    const int nh   = w >> 2;       // col half
    const int l4   = lane >> 2;
    const int lm   = lane & 3;

    const float* qb = q + ((size_t)b * LQ + q0) * DH;
    const float* kb = k + (size_t)b * LK * DH;

    const int r0 = wg * 16 + l4;
    const int r1 = r0 + 8;

    // ---- A fragments (q): permuted K-index mapping + truncation-bias correction ----
    // logical col lm   -> physical d = s*8 + 2*lm
    // logical col lm+4 -> physical d = s*8 + 2*lm + 1
    unsigned Af[8][4];
    #pragma unroll
    for (int s = 0; s < 8; s++) {
        Af[s][0] = cvt_tf32(TRUNC_CORR * qb[(size_t)r0 * DH + s * 8 + 2 * lm]);
        Af[s][1] = cvt_tf32(TRUNC_CORR * qb[(size_t)r1 * DH + s * 8 + 2 * lm]);
        Af[s][2] = cvt_tf32(TRUNC_CORR * qb[(size_t)r0 * DH + s * 8 + 2 * lm + 1]);
        Af[s][3] = cvt_tf32(TRUNC_CORR * qb[(size_t)r1 * DH + s * 8 + 2 * lm + 1]);
    }

    const float C = 0.18033688011112042f;   // 0.125 * log2(e)
    float sum0 = 0.0f, sum1 = 0.0f;

    float4* az = 0;
    if (write_attn)
        az = (float4*)(out + attn_off + ((size_t)b * LQ + q0) * LK);

    // smem byte addresses of this thread's 4 cp.async destinations per buffer
    uint32_t dst[2][4];
    #pragma unroll
    for (int i = 0; i < 4; i++) {
        int fi   = tid + i * NT;               // 0..1023 (16B chunks)
        int kr   = fi >> 4;
        int c4   = fi & 15;
        dst[0][i] = (uint32_t)__cvta_generic_to_shared(&ks[0][kr][c4 * 4]);
        dst[1][i] = (uint32_t)__cvta_generic_to_shared(&ks[1][kr][c4 * 4]);
    }

    // ---- prologue: fill buffer 0 with tile 0 ----
    #pragma unroll
    for (int i = 0; i < 4; i++) {
        int fi = tid + i * NT;
        cp_async16(dst[0][i], kb + (size_t)fi * 4);
    }
    CP_COMMIT();
    CP_WAIT0();
    __syncthreads();

    // ================= mainloop: double-buffered pipeline =================
    for (int t = 0; t < NTILES; t++) {
        const int cur = t & 1;

        // issue next tile's copies into the other buffer (overlaps compute)
        if (t + 1 < NTILES) {
            const float* src = kb + (size_t)(t + 1) * BK * DH;
            #pragma unroll
            for (int i = 0; i < 4; i++) {
                int fi = tid + i * NT;
                cp_async16(dst[cur ^ 1][i], src + (size_t)fi * 4);
            }
            CP_COMMIT();
        }

        // combine tilemax for tile t-1 (staged last iteration, sync'd since)
        if (t > 0 && tid < BQ)
            tilemax[tid][t - 1] = fmaxf(tmstage[cur ^ 1][0][tid],
                                        tmstage[cur ^ 1][1][tid]);

        // ---- compute: 16 rows x 32 cols per warp on buffer cur ----
        float acc[4][4];
        #pragma unroll
        for (int nc = 0; nc < 4; nc++)
            #pragma unroll
            for (int c = 0; c < 4; c++) acc[nc][c] = 0.0f;

        #pragma unroll
        for (int nc = 0; nc < 4; nc++) {
            const float* rp = &ks[cur][nh * 32 + nc * 8 + l4][lm * 2];
            #pragma unroll
            for (int s = 0; s < 8; s++) {
                // one LDS.64: physical words s*8+2lm, s*8+2lm+1 (raw bits as tf32)
                unsigned long long bv = *(const unsigned long long*)(rp + s * 8);
                mma_tf32(acc[nc], Af[s][0], Af[s][1], Af[s][2], Af[s][3],
                         (unsigned)(bv & 0xffffffffu), (unsigned)(bv >> 32));
            }
        }

        // ---- epilogue: max + exp-sum over this warp's 32 cols ----
        float tm0 = -1e30f, tm1 = -1e30f;
        #pragma unroll
        for (int nc = 0; nc < 4; nc++) {
            tm0 = fmaxf(tm0, fmaxf(acc[nc][0], acc[nc][1]));
            tm1 = fmaxf(tm1, fmaxf(acc[nc][2], acc[nc][3]));
            sum0 += ex2a(acc[nc][0] * C) + ex2a(acc[nc][1] * C);
            sum1 += ex2a(acc[nc][2] * C) + ex2a(acc[nc][3] * C);
        }
        #pragma unroll
        for (int off = 1; off <= 2; off <<= 1) {
            tm0 = fmaxf(tm0, __shfl_xor_sync(0xffffffffu, tm0, off));
            tm1 = fmaxf(tm1, __shfl_xor_sync(0xffffffffu, tm1, off));
        }
        if (lm == 0) { tmstage[cur][nh][r0] = tm0; tmstage[cur][nh][r1] = tm1; }

        // ---- interleaved zero-fill of this tile's attn chunk ----
        if (write_attn) {
            float4* azc = az + (size_t)t * (BQ * BK / 4);
            #pragma unroll
            for (int j = 0; j < 4; j++)
                azc[tid + j * NT] = make_float4(0.f, 0.f, 0.f, 0.f);
        }

        if (t + 1 < NTILES) CP_WAIT0();   // next buffer filled
        __syncthreads();
    }
    // combine last tile's max
    if (tid < BQ)
        tilemax[tid][NTILES - 1] = fmaxf(tmstage[(NTILES - 1) & 1][0][tid],
                                         tmstage[(NTILES - 1) & 1][1][tid]);

    // partial row sums per col-half
    #pragma unroll
    for (int off = 1; off <= 2; off <<= 1) {
        sum0 += __shfl_xor_sync(0xffffffffu, sum0, off);
        sum1 += __shfl_xor_sync(0xffffffffu, sum1, off);
    }
    if (lm == 0) { rs[nh][r0] = sum0; rs[nh][r1] = sum1; }
    __syncthreads();

    if (tid < BQ) rowsum[tid] = rs[0][tid] + rs[1][tid];
    __syncthreads();

    // ================= repair: one warp per row, warp-uniform branches =================
    #pragma unroll 1
    for (int rr8 = 0; rr8 < BQ / 8; rr8++) {
        const int r = w * 8 + rr8;

        const float tmv = tilemax[r][lane];      // 32 lanes = 32 tiles
        float best = tmv;
        #pragma unroll
        for (int off = 16; off > 0; off >>= 1)
            best = fmaxf(best, __shfl_xor_sync(0xffffffffu, best, off));
        const float thr = best - REPAIR_EPS;

        const float4 qv = *(const float4*)(qb + (size_t)r * DH + (lane & 15) * 4);

        float bm = -1e30f;
        int   bi = 0;
        #pragma unroll 1
        for (int t = 0; t < NTILES; t++) {
            if (__shfl_sync(0xffffffffu, tmv, t) < thr) continue;   // warp-uniform
            const float* kt = kb + (size_t)t * BK * DH;
            #pragma unroll 4
            for (int rr = 0; rr < 32; rr++) {
                const int col = rr * 2 + (lane >> 4);
                const float4 kv = *(const float4*)(kt + (size_t)col * DH + (lane & 15) * 4);
                float p = fmaf(qv.x, kv.x, fmaf(qv.y, kv.y,
                          fmaf(qv.z, kv.z, qv.w * kv.w)));
                p += __shfl_xor_sync(0xffffffffu, p, 8, 16);
                p += __shfl_xor_sync(0xffffffffu, p, 4, 16);
                p += __shfl_xor_sync(0xffffffffu, p, 2, 16);
                p += __shfl_xor_sync(0xffffffffu, p, 1, 16);
                if (p > bm) { bm = p; bi = t * BK + col; }  // strict > : lowest t/col kept
            }
        }
        #pragma unroll
        for (int off = 16; off > 0; off >>= 1) {
            float om = __shfl_xor_sync(0xffffffffu, bm, off);
            int   oi = __shfl_xor_sync(0xffffffffu, bi, off);
            if (om > bm || (om == bm && oi < bi)) { bm = om; bi = oi; }
        }
        if (lane == 0) {
            float p = ex2a(bm * C) / rowsum[r];
            pval[r] = p;
            widx[r] = bi;
            if (write_attn)
                out[attn_off + ((size_t)b * LQ + q0 + r) * LK + bi] = p;
        }
    }
    __syncthreads();

    // ================= dense output =================
    if (write_out) {
        #pragma unroll
        for (int i = tid; i < BQ * (DH / 4); i += NT) {
            const int r = i >> 4;
            const int c = i & 15;
            const float p = pval[r];
            const float4 vv = *(const float4*)(v + ((size_t)b * LK + widx[r]) * DH + c * 4);
            float4 o;
            o.x = p * vv.x; o.y = p * vv.y; o.z = p * vv.z; o.w = p * vv.w;
            *(float4*)(out + ((size_t)b * LQ + q0 + r) * DH + c * 4) = o;
        }
    }
}

extern "C" void kernel_launch(void* const* d_in, const int* in_sizes, int n_in,
                              void* d_out, int out_size)
{
    const float* q = (const float*)d_in[0];
    const float* k = (const float*)d_in[1];
    const float* v = (const float*)d_in[2];
    float* out = (float*)d_out;

    int wout = 0, wattn = 0;
    long long aoff = 0;
    size_t osz = (size_t)out_size;
    if (osz == OUT_ELEMS + ATTN_ELEMS) { wout = 1; wattn = 1; aoff = (long long)OUT_ELEMS; }
    else if (osz == ATTN_ELEMS)        { wattn = 1; aoff = 0; }
    else                               { wout = 1; }

    dim3 grid(LQ / BQ, BATCH);
    wta_attn13_kernel<<<grid, NT>>>(q, k, v, out, wout, wattn, aoff);
}